// round 1
// baseline (speedup 1.0000x reference)
#include <cuda_runtime.h>

#define NN   50000
#define EE   400000
#define EMB  32
#define NREL 8
#define NLAY 5
#define WPB  8            // warps per block (256 threads)

// ---------------- scratch (static device globals; no allocations) ----------
__device__ float g_We[(size_t)EE * EMB * EMB];   // 1.6 GB, per-edge 32x32 weight
__device__ float g_h[2][NN * EMB];               // double-buffered node features
__device__ float g_disc[NN * EMB];               // RGCN: root + bias + agg
__device__ float g_agg[NN * EMB];                // NNConv aggregate
__device__ float g_nnroot[NN * EMB];             // NNConv root part
__device__ float g_Xr[NREL][NN * EMB];           // per-relation h @ W_r
__device__ float g_invdeg[NN];
__device__ float g_invrel[NREL][NN];

// ---------------- degree / per-relation counts ------------------------------
__global__ void zero_counts_kernel() {
    int i = blockIdx.x * blockDim.x + threadIdx.x;
    if (i < NN) g_invdeg[i] = 0.f;
    if (i < NN * NREL) ((float*)g_invrel)[i] = 0.f;
}

__global__ void count_kernel(const int* __restrict__ dst,
                             const int* __restrict__ etype) {
    int e = blockIdx.x * blockDim.x + threadIdx.x;
    if (e >= EE) return;
    int d = dst[e], r = etype[e];
    atomicAdd(&g_invdeg[d], 1.f);
    atomicAdd(&g_invrel[r][d], 1.f);
}

__global__ void invert_kernel() {
    int i = blockIdx.x * blockDim.x + threadIdx.x;
    if (i < NN) g_invdeg[i] = 1.f / fmaxf(g_invdeg[i], 1.f);
    if (i < NN * NREL) {
        float v = ((float*)g_invrel)[i];
        ((float*)g_invrel)[i] = 1.f / fmaxf(v, 1.f);
    }
}

// ---------------- We = relu(dist*W1[0] + W1[1+r] + b1) @ W2 + b2 ------------
// grid: (ceil(E/WPB), 4 column chunks of 256).  smem tile of W2: 32x256 = 32KB.
__global__ __launch_bounds__(WPB * 32) void we_kernel(
    const int* __restrict__ etype, const float* __restrict__ edist,
    const float* __restrict__ W1, const float* __restrict__ b1,
    const float* __restrict__ W2, const float* __restrict__ b2) {
    __shared__ float sW2[32][256];
    int c0 = blockIdx.y * 256;
    for (int idx = threadIdx.x; idx < 32 * 256; idx += blockDim.x) {
        int k = idx >> 8, c = idx & 255;
        sW2[k][c] = W2[k * 1024 + c0 + c];
    }
    __syncthreads();

    int warp = threadIdx.x >> 5, lane = threadIdx.x & 31;
    int e = blockIdx.x * WPB + warp;
    if (e >= EE) return;

    int   r = etype[e];
    float d = edist[e];
    float hid = fmaxf(d * W1[lane] + W1[(1 + r) * 32 + lane] + b1[lane], 0.f);

    float acc[8];
#pragma unroll
    for (int j = 0; j < 8; j++) acc[j] = b2[c0 + lane + 32 * j];
#pragma unroll
    for (int k = 0; k < 32; k++) {
        float hv = __shfl_sync(0xffffffffu, hid, k);
#pragma unroll
        for (int j = 0; j < 8; j++)
            acc[j] = fmaf(hv, sW2[k][lane + 32 * j], acc[j]);
    }
    float* dst = &g_We[(size_t)e * 1024 + c0];
#pragma unroll
    for (int j = 0; j < 8; j++) dst[lane + 32 * j] = acc[j];
}

// ---------------- h0 = relu(x @ fc_W + fc_b) --------------------------------
__global__ __launch_bounds__(WPB * 32) void fc_kernel(
    const float* __restrict__ x, const float* __restrict__ W,
    const float* __restrict__ b) {
    int warp = threadIdx.x >> 5, lane = threadIdx.x & 31;
    int n = blockIdx.x * WPB + warp;
    if (n >= NN) return;
    float xv = x[n * 32 + lane];
    float acc = b[lane];
#pragma unroll
    for (int k = 0; k < 32; k++)
        acc = fmaf(__shfl_sync(0xffffffffu, xv, k), W[k * 32 + lane], acc);
    g_h[0][n * 32 + lane] = fmaxf(acc, 0.f);
}

// ---------------- per-layer node transforms (10 small matvecs) --------------
__global__ __launch_bounds__(WPB * 32) void node_kernel(
    int p,
    const float* __restrict__ rW,    // [R,32,32] for this layer
    const float* __restrict__ rroot, // [32,32]
    const float* __restrict__ rbias, // [32]
    const float* __restrict__ nroot, // [32,32]
    const float* __restrict__ nbias) // [32]
{
    int warp = threadIdx.x >> 5, lane = threadIdx.x & 31;
    int n = blockIdx.x * WPB + warp;
    if (n >= NN) return;
    float hv = g_h[p][n * 32 + lane];
    float accD = rbias[lane];
    float accN = nbias[lane];
    float accR[NREL];
#pragma unroll
    for (int r = 0; r < NREL; r++) accR[r] = 0.f;
#pragma unroll
    for (int k = 0; k < 32; k++) {
        float v = __shfl_sync(0xffffffffu, hv, k);
        accD = fmaf(v, rroot[k * 32 + lane], accD);
        accN = fmaf(v, nroot[k * 32 + lane], accN);
#pragma unroll
        for (int r = 0; r < NREL; r++)
            accR[r] = fmaf(v, rW[r * 1024 + k * 32 + lane], accR[r]);
    }
    g_disc[n * 32 + lane]   = accD;
    g_nnroot[n * 32 + lane] = accN;
#pragma unroll
    for (int r = 0; r < NREL; r++) g_Xr[r][n * 32 + lane] = accR[r];
    g_agg[n * 32 + lane] = 0.f;
}

// ---------------- per-layer edge scatter (RGCN + NNConv) --------------------
__global__ __launch_bounds__(WPB * 32) void edge_kernel(
    int p, const int* __restrict__ src, const int* __restrict__ dst_,
    const int* __restrict__ etype) {
    int warp = threadIdx.x >> 5, lane = threadIdx.x & 31;
    int e = blockIdx.x * WPB + warp;
    if (e >= EE) return;
    int s = src[e], d = dst_[e], r = etype[e];

    // RGCN message: (h @ W_r)[s] / rel_cnt[r][d]
    float rv = g_Xr[r][s * 32 + lane] * g_invrel[r][d];
    atomicAdd(&g_disc[d * 32 + lane], rv);

    // NNConv message: h[s] @ We[e]
    float hs = g_h[p][s * 32 + lane];
    const float* we = &g_We[(size_t)e * 1024];
    float m = 0.f;
#pragma unroll
    for (int i = 0; i < 32; i++) {
        float hv = __shfl_sync(0xffffffffu, hs, i);
        m = fmaf(hv, we[i * 32 + lane], m);
    }
    atomicAdd(&g_agg[d * 32 + lane], m * g_invdeg[d]);
}

// ---------------- combine: h += relu(disc) + relu(nnroot + agg) -------------
__global__ void combine_kernel(int p, float* __restrict__ out_final) {
    int idx = blockIdx.x * blockDim.x + threadIdx.x;
    if (idx >= NN * EMB) return;
    float v = g_h[p][idx] + fmaxf(g_disc[idx], 0.f)
            + fmaxf(g_nnroot[idx] + g_agg[idx], 0.f);
    if (out_final) out_final[idx] = v;
    else           g_h[p ^ 1][idx] = v;
}

// ---------------- host launch ------------------------------------------------
extern "C" void kernel_launch(void* const* d_in, const int* in_sizes, int n_in,
                              void* d_out, int out_size) {
    const float* x     = (const float*)d_in[0];
    const int*   eidx  = (const int*)  d_in[1];   // [2,E]: src then dst
    const int*   etype = (const int*)  d_in[2];
    const float* edist = (const float*)d_in[3];
    const float* fcW   = (const float*)d_in[4];
    const float* fcb   = (const float*)d_in[5];
    const float* rW    = (const float*)d_in[6];   // [L,R,32,32]
    const float* rroot = (const float*)d_in[7];   // [L,32,32]
    const float* rbias = (const float*)d_in[8];   // [L,32]
    const float* W1    = (const float*)d_in[9];   // [9,32]
    const float* b1    = (const float*)d_in[10];  // [32]
    const float* W2    = (const float*)d_in[11];  // [32,1024]
    const float* b2    = (const float*)d_in[12];  // [1024]
    const float* nroot = (const float*)d_in[13];  // [L,32,32]
    const float* nbias = (const float*)d_in[14];  // [L,32]
    float* out = (float*)d_out;

    const int* srcp = eidx;
    const int* dstp = eidx + EE;

    int nthread_cnt = NN * NREL;  // covers both invdeg (NN) and invrel (NN*R)

    zero_counts_kernel<<<(nthread_cnt + 255) / 256, 256>>>();
    count_kernel<<<(EE + 255) / 256, 256>>>(dstp, etype);
    invert_kernel<<<(nthread_cnt + 255) / 256, 256>>>();

    // Per-edge weight matrices (layer-invariant): build once.
    we_kernel<<<dim3((EE + WPB - 1) / WPB, 4), WPB * 32>>>(etype, edist, W1, b1, W2, b2);

    // Initial embedding.
    fc_kernel<<<(NN + WPB - 1) / WPB, WPB * 32>>>(x, fcW, fcb);

    for (int l = 0; l < NLAY; l++) {
        int p = l & 1;
        node_kernel<<<(NN + WPB - 1) / WPB, WPB * 32>>>(
            p,
            rW    + (size_t)l * NREL * EMB * EMB,
            rroot + (size_t)l * EMB * EMB,
            rbias + (size_t)l * EMB,
            nroot + (size_t)l * EMB * EMB,
            nbias + (size_t)l * EMB);
        edge_kernel<<<(EE + WPB - 1) / WPB, WPB * 32>>>(p, srcp, dstp, etype);
        combine_kernel<<<(NN * EMB + 255) / 256, 256>>>(
            p, (l == NLAY - 1) ? out : nullptr);
    }
}

// round 2
// speedup vs baseline: 2.4806x; 2.4806x over previous
#include <cuda_runtime.h>

#define NN   50000
#define EE   400000
#define EMB  32
#define NREL 8
#define NLAY 5
#define WPB  8            // warps per block (256 threads)

// ---------------- scratch (static device globals; no allocations) ----------
__device__ float g_G[(size_t)NN * 1024];         // 200 MB: per-node G[k][o]
__device__ float g_W2t[32 * 1024];               // W2 transposed to [i][(k,o)]
__device__ float g_h[2][NN * EMB];
__device__ float g_disc[NN * EMB];
__device__ float g_agg[NN * EMB];
__device__ float g_nnroot[NN * EMB];
__device__ float g_invdeg[NN];
__device__ float g_invrel[NREL][NN];
// CSR by source
__device__ int   g_outdeg[NN];
__device__ int   g_cursor[NN];
__device__ int   g_rowptr[NN + 1];
__device__ int   g_ceid[EE];
__device__ int   g_cdst[EE];
__device__ int   g_crel[EE];
__device__ float g_cwn[EE];                      // invdeg[dst]
__device__ float g_cwr[EE];                      // invrel[r][dst]
__device__ float g_chid[(size_t)EE * 32];        // per-edge hidden (layer-invariant)

// ---------------- zero / counts ---------------------------------------------
__global__ void zero_counts_kernel() {
    int i = blockIdx.x * blockDim.x + threadIdx.x;
    if (i < NN) { g_invdeg[i] = 0.f; g_outdeg[i] = 0; }
    if (i < NN * NREL) ((float*)g_invrel)[i] = 0.f;
}

__global__ void count_kernel(const int* __restrict__ src,
                             const int* __restrict__ dst,
                             const int* __restrict__ etype) {
    int e = blockIdx.x * blockDim.x + threadIdx.x;
    if (e >= EE) return;
    int d = dst[e], r = etype[e];
    atomicAdd(&g_invdeg[d], 1.f);
    atomicAdd(&g_invrel[r][d], 1.f);
    atomicAdd(&g_outdeg[src[e]], 1);
}

__global__ void invert_kernel() {
    int i = blockIdx.x * blockDim.x + threadIdx.x;
    if (i < NN) g_invdeg[i] = 1.f / fmaxf(g_invdeg[i], 1.f);
    if (i < NN * NREL) {
        float v = ((float*)g_invrel)[i];
        ((float*)g_invrel)[i] = 1.f / fmaxf(v, 1.f);
    }
}

// ---------------- exclusive scan of outdeg -> rowptr (one block) ------------
#define SCAN_T 1024
#define CHUNK  49   // 1024*49 >= 50000
__global__ __launch_bounds__(SCAN_T) void scan_kernel() {
    __shared__ int ssum[SCAN_T];
    int t = threadIdx.x, base = t * CHUNK;
    int s = 0;
    for (int j = 0; j < CHUNK; j++) {
        int idx = base + j;
        if (idx < NN) s += g_outdeg[idx];
    }
    ssum[t] = s;
    __syncthreads();
    for (int off = 1; off < SCAN_T; off <<= 1) {
        int v = (t >= off) ? ssum[t - off] : 0;
        __syncthreads();
        ssum[t] += v;
        __syncthreads();
    }
    int run = ssum[t] - s;  // exclusive prefix of this chunk
    for (int j = 0; j < CHUNK; j++) {
        int idx = base + j;
        if (idx < NN) {
            g_rowptr[idx] = run;
            g_cursor[idx] = 0;
            run += g_outdeg[idx];
        }
    }
    if (t == 0) g_rowptr[NN] = EE;
}

// ---------------- fill CSR ---------------------------------------------------
__global__ void fill_kernel(const int* __restrict__ src,
                            const int* __restrict__ dst,
                            const int* __restrict__ etype) {
    int e = blockIdx.x * blockDim.x + threadIdx.x;
    if (e >= EE) return;
    int s = src[e];
    int pos = g_rowptr[s] + atomicAdd(&g_cursor[s], 1);
    g_ceid[pos] = e;
    g_cdst[pos] = dst[e];
    g_crel[pos] = etype[e];
}

// ---------------- per-edge hidden (layer-invariant) + scales ----------------
__global__ __launch_bounds__(WPB * 32) void hid_kernel(
    const int* __restrict__ etype, const float* __restrict__ edist,
    const float* __restrict__ W1, const float* __restrict__ b1) {
    int warp = threadIdx.x >> 5, lane = threadIdx.x & 31;
    int pos = blockIdx.x * WPB + warp;
    if (pos >= EE) return;
    int e = g_ceid[pos];
    int r = etype[e];
    float dd = edist[e];
    float h = fmaxf(dd * W1[lane] + W1[(1 + r) * 32 + lane] + b1[lane], 0.f);
    g_chid[(size_t)pos * 32 + lane] = h;
    if (lane == 0) {
        int dn = g_cdst[pos];
        g_cwn[pos] = g_invdeg[dn];
        g_cwr[pos] = g_invrel[r][dn];
    }
}

// ---------------- transpose W2: g_W2t[i][(k,o)] = W2[k][i*32+o] -------------
__global__ void w2t_kernel(const float* __restrict__ W2) {
    int idx = blockIdx.x * blockDim.x + threadIdx.x;
    if (idx >= 32 * 1024) return;
    int i = idx >> 10, rest = idx & 1023;   // rest = k*32+o
    int k = rest >> 5, o = rest & 31;
    g_W2t[idx] = W2[k * 1024 + i * 32 + o];
}

// ---------------- h0 = relu(x @ fc_W + fc_b) --------------------------------
__global__ __launch_bounds__(WPB * 32) void fc_kernel(
    const float* __restrict__ x, const float* __restrict__ W,
    const float* __restrict__ b) {
    int warp = threadIdx.x >> 5, lane = threadIdx.x & 31;
    int n = blockIdx.x * WPB + warp;
    if (n >= NN) return;
    float xv = x[n * 32 + lane];
    float acc = b[lane];
#pragma unroll
    for (int k = 0; k < 32; k++)
        acc = fmaf(__shfl_sync(0xffffffffu, xv, k), W[k * 32 + lane], acc);
    g_h[0][n * 32 + lane] = fmaxf(acc, 0.f);
}

// ---------------- G = h @ W2t : [N,32]@[32,1024], register-tiled ------------
// grid (ceil(N/32), 4), block 256. Tile: 32 nodes x 256 cols.
__global__ __launch_bounds__(256) void gemmG_kernel(int p) {
    __shared__ float sh[32][33];
    __shared__ float sW[32][256];
    int t = threadIdx.x;
    int n0 = blockIdx.x * 32;
    int c0 = blockIdx.y * 256;

    {   // load h tile (32x32) as float4
        int node = t >> 3, k = (t & 7) * 4;
        float4 v = make_float4(0.f, 0.f, 0.f, 0.f);
        if (n0 + node < NN)
            v = *(const float4*)&g_h[p][(size_t)(n0 + node) * 32 + k];
        sh[node][k] = v.x; sh[node][k + 1] = v.y;
        sh[node][k + 2] = v.z; sh[node][k + 3] = v.w;
    }
#pragma unroll
    for (int j = 0; j < 8; j++) {   // load W2t chunk 32x256 as float4
        int f4 = t + j * 256;            // float4 index
        int flat = f4 * 4;
        int k = flat >> 8, c = flat & 255;
        *(float4*)&sW[k][c] = *(const float4*)&g_W2t[k * 1024 + c0 + c];
    }
    __syncthreads();

    int lane = t & 31, wg = t >> 5;     // node group
    float acc[4][8];
#pragma unroll
    for (int j = 0; j < 4; j++)
#pragma unroll
        for (int c = 0; c < 8; c++) acc[j][c] = 0.f;

#pragma unroll
    for (int k = 0; k < 32; k++) {
        float a0 = sh[wg * 4 + 0][k];
        float a1 = sh[wg * 4 + 1][k];
        float a2 = sh[wg * 4 + 2][k];
        float a3 = sh[wg * 4 + 3][k];
#pragma unroll
        for (int c = 0; c < 8; c++) {
            float w = sW[k][lane + 32 * c];
            acc[0][c] = fmaf(a0, w, acc[0][c]);
            acc[1][c] = fmaf(a1, w, acc[1][c]);
            acc[2][c] = fmaf(a2, w, acc[2][c]);
            acc[3][c] = fmaf(a3, w, acc[3][c]);
        }
    }
#pragma unroll
    for (int j = 0; j < 4; j++) {
        int n = n0 + wg * 4 + j;
        if (n < NN) {
#pragma unroll
            for (int c = 0; c < 8; c++)
                g_G[(size_t)n * 1024 + c0 + lane + 32 * c] = acc[j][c];
        }
    }
}

// ---------------- per-layer node transforms ---------------------------------
__global__ __launch_bounds__(WPB * 32) void node_kernel(
    int p, const float* __restrict__ rroot, const float* __restrict__ rbias,
    const float* __restrict__ nroot, const float* __restrict__ nbias) {
    int warp = threadIdx.x >> 5, lane = threadIdx.x & 31;
    int n = blockIdx.x * WPB + warp;
    if (n >= NN) return;
    float hv = g_h[p][n * 32 + lane];
    float accD = rbias[lane];
    float accN = nbias[lane];
#pragma unroll
    for (int k = 0; k < 32; k++) {
        float v = __shfl_sync(0xffffffffu, hv, k);
        accD = fmaf(v, rroot[k * 32 + lane], accD);
        accN = fmaf(v, nroot[k * 32 + lane], accN);
    }
    g_disc[n * 32 + lane]   = accD;
    g_nnroot[n * 32 + lane] = accN;
    g_agg[n * 32 + lane]    = 0.f;
}

// ---------------- fused per-layer edge kernel (warp per source) -------------
__global__ __launch_bounds__(WPB * 32) void edge_kernel(
    int p, const float* __restrict__ rW,   // [R,32,32] this layer
    const float* __restrict__ b2) {
    __shared__ float sWr[NREL * 1024];     // 32 KB
    __shared__ float sXr[WPB][NREL][32];   // 8 KB
    __shared__ float sb2[1024];            // 4 KB

    int t = threadIdx.x;
#pragma unroll
    for (int j = 0; j < 8; j++) {
        int f4 = t + j * 256;
        *(float4*)&sWr[f4 * 4] = *(const float4*)&rW[f4 * 4];
    }
    *(float4*)&sb2[t * 4] = *(const float4*)&b2[t * 4];
    __syncthreads();

    int warp = t >> 5, lane = t & 31;
    int n = blockIdx.x * WPB + warp;
    if (n >= NN) return;

    float hs = g_h[p][n * 32 + lane];

    // preload G row into registers (coalesced: lane fastest)
    const float* grow = &g_G[(size_t)n * 1024];
    float Greg[32];
#pragma unroll
    for (int k = 0; k < 32; k++) Greg[k] = grow[k * 32 + lane];

    // precompute RGCN messages for all relations + bias term B
    float xr[NREL];
#pragma unroll
    for (int r = 0; r < NREL; r++) xr[r] = 0.f;
    float B = 0.f;
#pragma unroll
    for (int i = 0; i < 32; i++) {
        float hv = __shfl_sync(0xffffffffu, hs, i);
        B = fmaf(hv, sb2[i * 32 + lane], B);
#pragma unroll
        for (int r = 0; r < NREL; r++)
            xr[r] = fmaf(hv, sWr[r * 1024 + i * 32 + lane], xr[r]);
    }
#pragma unroll
    for (int r = 0; r < NREL; r++) sXr[warp][r][lane] = xr[r];
    __syncwarp();

    int beg = g_rowptr[n], end = g_rowptr[n + 1];
    for (int pos = beg; pos < end; pos++) {
        int   d  = g_cdst[pos];
        int   r  = g_crel[pos];
        float wn = g_cwn[pos];
        float wr = g_cwr[pos];
        float hid = g_chid[(size_t)pos * 32 + lane];

        float m0 = 0.f, m1 = 0.f, m2 = 0.f, m3 = 0.f;
#pragma unroll
        for (int k = 0; k < 32; k += 4) {
            m0 = fmaf(__shfl_sync(0xffffffffu, hid, k + 0), Greg[k + 0], m0);
            m1 = fmaf(__shfl_sync(0xffffffffu, hid, k + 1), Greg[k + 1], m1);
            m2 = fmaf(__shfl_sync(0xffffffffu, hid, k + 2), Greg[k + 2], m2);
            m3 = fmaf(__shfl_sync(0xffffffffu, hid, k + 3), Greg[k + 3], m3);
        }
        float m = (m0 + m1) + (m2 + m3) + B;
        float rm = sXr[warp][r][lane];

        atomicAdd(&g_disc[(size_t)d * 32 + lane], rm * wr);
        atomicAdd(&g_agg[(size_t)d * 32 + lane],  m * wn);
    }
}

// ---------------- combine ----------------------------------------------------
__global__ void combine_kernel(int p, float* __restrict__ out_final) {
    int idx = blockIdx.x * blockDim.x + threadIdx.x;
    if (idx >= NN * EMB) return;
    float v = g_h[p][idx] + fmaxf(g_disc[idx], 0.f)
            + fmaxf(g_nnroot[idx] + g_agg[idx], 0.f);
    if (out_final) out_final[idx] = v;
    else           g_h[p ^ 1][idx] = v;
}

// ---------------- host launch ------------------------------------------------
extern "C" void kernel_launch(void* const* d_in, const int* in_sizes, int n_in,
                              void* d_out, int out_size) {
    const float* x     = (const float*)d_in[0];
    const int*   eidx  = (const int*)  d_in[1];   // [2,E]: src then dst
    const int*   etype = (const int*)  d_in[2];
    const float* edist = (const float*)d_in[3];
    const float* fcW   = (const float*)d_in[4];
    const float* fcb   = (const float*)d_in[5];
    const float* rW    = (const float*)d_in[6];   // [L,R,32,32]
    const float* rroot = (const float*)d_in[7];   // [L,32,32]
    const float* rbias = (const float*)d_in[8];   // [L,32]
    const float* W1    = (const float*)d_in[9];   // [9,32]
    const float* b1    = (const float*)d_in[10];  // [32]
    const float* W2    = (const float*)d_in[11];  // [32,1024]
    const float* b2    = (const float*)d_in[12];  // [1024]
    const float* nroot = (const float*)d_in[13];  // [L,32,32]
    const float* nbias = (const float*)d_in[14];  // [L,32]
    float* out = (float*)d_out;

    const int* srcp = eidx;
    const int* dstp = eidx + EE;

    int cnt = NN * NREL;
    zero_counts_kernel<<<(cnt + 255) / 256, 256>>>();
    count_kernel<<<(EE + 255) / 256, 256>>>(srcp, dstp, etype);
    invert_kernel<<<(cnt + 255) / 256, 256>>>();
    scan_kernel<<<1, SCAN_T>>>();
    fill_kernel<<<(EE + 255) / 256, 256>>>(srcp, dstp, etype);
    hid_kernel<<<(EE + WPB - 1) / WPB, WPB * 32>>>(etype, edist, W1, b1);
    w2t_kernel<<<(32 * 1024 + 255) / 256, 256>>>(W2);
    fc_kernel<<<(NN + WPB - 1) / WPB, WPB * 32>>>(x, fcW, fcb);

    for (int l = 0; l < NLAY; l++) {
        int p = l & 1;
        gemmG_kernel<<<dim3((NN + 31) / 32, 4), 256>>>(p);
        node_kernel<<<(NN + WPB - 1) / WPB, WPB * 32>>>(
            p, rroot + (size_t)l * 1024, rbias + (size_t)l * 32,
            nroot + (size_t)l * 1024, nbias + (size_t)l * 32);
        edge_kernel<<<(NN + WPB - 1) / WPB, WPB * 32>>>(
            p, rW + (size_t)l * NREL * 1024, b2);
        combine_kernel<<<(NN * EMB + 255) / 256, 256>>>(
            p, (l == NLAY - 1) ? out : nullptr);
    }
}